// round 9
// baseline (speedup 1.0000x reference)
#include <cuda_runtime.h>
#include <float.h>

// ROI adaptive max pool 7x7 — channels-last restage, 2 kernels.
// images: [8,256,56,56] f32; rois: [256,4] f32; roi_idx: [256] i32
// out: [256,256,7,7] f32
//
// K1 transpose: [n][c][hw] -> g_timg [n][hw][c] via 32x32 smem tiles,
//    coalesced on both sides.
// K2 pool: block = (roi, 64-channel slab). tx = channel-quad (16 quads =
//    256B contiguous per bin-row position -> 100% lane + line utilization,
//    zero lane-predicate divergence). ty strides the 49 output bins.
//    Bin bounds computed in-block (28 threads). Output staged in smem,
//    coalesced float4 writeback.

#define Nn 8
#define Cc 256
#define Hc 56
#define Wc 56
#define HWc (Hc * Wc)      // 3136
#define Rc 256
#define OUTN 7
#define C4 (Cc / 4)        // 64 float4 per pixel

__device__ float g_timg[(size_t)Nn * HWc * Cc];   // ~25.7 MB channels-last

// ---- K1: transpose to channels-last ----
__global__ __launch_bounds__(256) void transpose_kernel(const float* __restrict__ images) {
    __shared__ float tile[32][33];
    const int hw0 = blockIdx.x * 32;
    const int c0  = blockIdx.y * 32;
    const int n   = blockIdx.z;
    const int tx = threadIdx.x, ty = threadIdx.y;

    const float* __restrict__ src = images + (size_t)n * Cc * HWc;
    #pragma unroll
    for (int k = 0; k < 4; k++)
        tile[ty + k * 8][tx] = src[(size_t)(c0 + ty + k * 8) * HWc + hw0 + tx];
    __syncthreads();
    float* __restrict__ dst = g_timg + (size_t)n * HWc * Cc;
    #pragma unroll
    for (int k = 0; k < 4; k++)
        dst[(size_t)(hw0 + ty + k * 8) * Cc + c0 + tx] = tile[tx][ty + k * 8];
}

// ---- K2: pool from channels-last ----
__global__ __launch_bounds__(256) void pool_kernel(
    const float* __restrict__ rois,
    const int* __restrict__ roi_idx,
    float* __restrict__ out)
{
    __shared__ int   sb[28];            // ys[7] ye[7] xs[7] xe[7]
    __shared__ float sout[64 * 49];     // [ch_local][bin]

    const int r   = blockIdx.y;
    const int cg  = blockIdx.x;         // 0..3, 64 channels each
    const int tx  = threadIdx.x;        // 0..15 channel-quad
    const int ty  = threadIdx.y;        // 0..15 bin-slice
    const int tid = ty * 16 + tx;

    const float4 rv = ((const float4*)rois)[r];
    const int x1 = (int)floorf(rv.x * (float)Wc);
    const int y1 = (int)floorf(rv.y * (float)Hc);
    const int x2 = (int)ceilf (rv.z * (float)Wc);
    const int y2 = (int)ceilf (rv.w * (float)Hc);

    if (tid < 28) {
        const int g = tid / OUTN;
        const int i = tid - g * OUTN;
        const int Hr = y2 - y1, Wr = x2 - x1;
        int v;
        if (g == 0)      v = y1 + (i * Hr) / OUTN;
        else if (g == 1) v = y1 + ((i + 1) * Hr + OUTN - 1) / OUTN;
        else if (g == 2) v = x1 + (i * Wr) / OUTN;
        else             v = x1 + ((i + 1) * Wr + OUTN - 1) / OUTN;
        sb[tid] = v;
    }
    __syncthreads();

    const int n = roi_idx[r];
    // float4 view of pixel p, channel-quad q: timg4[(n*HWc + p)*C4 + q]
    const float4* __restrict__ base =
        (const float4*)g_timg + (size_t)n * HWc * C4 + cg * 16 + tx;

    for (int b = ty; b < OUTN * OUTN; b += 16) {
        const int i = (b * 37) >> 8;        // b/7 for b<=48
        const int j = b - i * OUTN;
        const int ys = sb[i],      ye = sb[7 + i];
        const int xs = sb[14 + j], xe = sb[21 + j];
        float4 m = make_float4(-FLT_MAX, -FLT_MAX, -FLT_MAX, -FLT_MAX);
        for (int y = ys; y < ye; y++) {
            const float4* __restrict__ p = base + (size_t)(y * Wc + xs) * C4;
            #pragma unroll 2
            for (int x = xs; x < xe; x++) {
                const float4 v = *p; p += C4;
                m.x = fmaxf(m.x, v.x);
                m.y = fmaxf(m.y, v.y);
                m.z = fmaxf(m.z, v.z);
                m.w = fmaxf(m.w, v.w);
            }
        }
        const int cl = tx * 4;
        sout[(cl + 0) * 49 + b] = m.x;
        sout[(cl + 1) * 49 + b] = m.y;
        sout[(cl + 2) * 49 + b] = m.z;
        sout[(cl + 3) * 49 + b] = m.w;
    }
    __syncthreads();

    // Coalesced writeback of the contiguous [64ch x 49] slab.
    float4* __restrict__ og = (float4*)(out + ((size_t)r * Cc + cg * 64) * 49);
    const float4* __restrict__ so4 = (const float4*)sout;
    #pragma unroll
    for (int idx = tid; idx < 64 * 49 / 4; idx += 256)
        og[idx] = so4[idx];
}

extern "C" void kernel_launch(void* const* d_in, const int* in_sizes, int n_in,
                              void* d_out, int out_size) {
    const float* images  = (const float*)d_in[0];
    const float* rois    = (const float*)d_in[1];
    const int*   roi_idx = (const int*)d_in[2];
    float* out = (float*)d_out;

    transpose_kernel<<<dim3(HWc / 32, Cc / 32, Nn), dim3(32, 8)>>>(images);
    pool_kernel<<<dim3(4, Rc), dim3(16, 16)>>>(rois, roi_idx, out);
}

// round 10
// speedup vs baseline: 1.2240x; 1.2240x over previous
#include <cuda_runtime.h>
#include <float.h>

// ROI adaptive max pool 7x7 — R5 mapping + static clamped-4-load bins
// (compile-time load batching -> MLP ~8-12 per thread).
// images: [8,256,56,56] f32; rois: [256,4] f32; roi_idx: [256] i32
// out: [256,256,7,7] f32

#define Hc 56
#define Wc 56
#define Cc 256
#define Rc 256
#define OUTN 7
#define CPB 16
#define W4 (Wc / 4)   // 14

__device__ __forceinline__ float4 fm4(float4 a, float4 b) {
    return make_float4(fmaxf(a.x, b.x), fmaxf(a.y, b.y),
                       fmaxf(a.z, b.z), fmaxf(a.w, b.w));
}

__global__ __launch_bounds__(256, 5) void roipool_kernel(
    const float* __restrict__ images,
    const float* __restrict__ rois,
    const int* __restrict__ roi_idx,
    float* __restrict__ out)
{
    __shared__ float rowp[CPB][OUTN][60];
    __shared__ int sb[28];   // ys[7] ye[7] xs[7] xe[7]

    const int r  = blockIdx.y;
    const int cg = blockIdx.x;
    const int tx = threadIdx.x;            // 0..15 quad
    const int ty = threadIdx.y;            // 0..15 channel
    const int tid = ty * 16 + tx;

    const float4 rv = ((const float4*)rois)[r];
    const int x1 = (int)floorf(rv.x * (float)Wc);
    const int y1 = (int)floorf(rv.y * (float)Hc);
    const int x2 = (int)ceilf (rv.z * (float)Wc);
    const int y2 = (int)ceilf (rv.w * (float)Hc);

    if (tid < 28) {
        const int g = tid / OUTN;          // 0:ys 1:ye 2:xs 3:xe
        const int i = tid - g * OUTN;
        const int Hr = y2 - y1, Wr = x2 - x1;
        int v;
        if (g == 0)      v = y1 + (i * Hr) / OUTN;
        else if (g == 1) v = y1 + ((i + 1) * Hr + OUTN - 1) / OUTN;
        else if (g == 2) v = x1 + (i * Wr) / OUTN;
        else             v = x1 + ((i + 1) * Wr + OUTN - 1) / OUTN;
        sb[tid] = v;
    }
    __syncthreads();

    const int n_img = roi_idx[r];
    const float* __restrict__ img =
        images + (size_t)(n_img * Cc + cg * CPB + ty) * (Hc * Wc);

    // ---- Phase 1: row-bin maxes, 4 static clamped loads per bin ----
    const int qlo = x1 >> 2;
    const int qhi = (x2 + 3) >> 2;
    if (tx >= qlo && tx < qhi) {
        const float4* __restrict__ base = (const float4*)img + tx;
        #pragma unroll
        for (int i = 0; i < OUTN; i++) {
            const int s = sb[i];
            const int n = sb[7 + i] - s;   // warp-uniform, >=1
            const float4* __restrict__ p = base + s * W4;
            // clamped offsets: duplicates when n<4 (L1-hot, cheap)
            const int c1 = (1 < n ? 1 : n - 1) * W4;
            const int c2 = (2 < n ? 2 : n - 1) * W4;
            const int c3 = (3 < n ? 3 : n - 1) * W4;
            const float4 a = p[0];
            const float4 b = p[c1];
            const float4 c = p[c2];
            const float4 d = p[c3];
            float4 m = fm4(fm4(a, b), fm4(c, d));
            // rare residual (n>4), warp-uniform branch
            if (n > 4) {
                #pragma unroll 2
                for (int y = 4; y < n; y++)
                    m = fm4(m, p[y * W4]);
            }
            *(float4*)&rowp[ty][i][tx * 4] = m;
        }
    }
    __syncthreads();

    // ---- Phase 2: col-bin maxes from shared, trip-count-specialized ----
    float* __restrict__ outg = out + ((size_t)r * Cc + cg * CPB) * (OUTN * OUTN);
    #pragma unroll
    for (int o = tid; o < CPB * OUTN * OUTN; o += 256) {
        const int cc = o / (OUTN * OUTN);
        const int ij = o - cc * (OUTN * OUTN);
        const int i = ij / OUTN;
        const int j = ij - i * OUTN;
        const int s = sb[14 + j];
        const int n = sb[21 + j] - s;      // >=1
        const float* __restrict__ rp = &rowp[cc][i][s];
        // 4 static clamped reads + rare residual
        const int c1 = (1 < n ? 1 : n - 1);
        const int c2 = (2 < n ? 2 : n - 1);
        const int c3 = (3 < n ? 3 : n - 1);
        float m = fmaxf(fmaxf(rp[0], rp[c1]), fmaxf(rp[c2], rp[c3]));
        if (n > 4) {
            #pragma unroll 2
            for (int x = 4; x < n; x++)
                m = fmaxf(m, rp[x]);
        }
        outg[o] = m;   // contiguous per stride-pass -> coalesced
    }
}

extern "C" void kernel_launch(void* const* d_in, const int* in_sizes, int n_in,
                              void* d_out, int out_size) {
    const float* images  = (const float*)d_in[0];
    const float* rois    = (const float*)d_in[1];
    const int*   roi_idx = (const int*)d_in[2];
    float* out = (float*)d_out;

    dim3 grid(Cc / CPB, Rc);   // (16, 256) = 4096 blocks
    dim3 block(16, 16);        // 256 threads
    roipool_kernel<<<grid, block>>>(images, rois, roi_idx, out);
}